// round 12
// baseline (speedup 1.0000x reference)
#include <cuda_runtime.h>
#include <math.h>

#define V 720
#define QV 180
#define U 736
#define NXY 512
#define NPIX (NXY * NXY)
#define NTAPS 368

#define DU_D   1.2858
#define DSO_D  595.0
#define DOD_D  490.6
#define DSD_D  (DSO_D + DOD_D)
#define SVOX_D 400.0
#define PI_D   3.14159265358979323846

// parity-packed conv arrays
#define PADE 380
#define PODD 383
#define WLEN 1124

// guard-band padded filtered rows: slot i holds detector index u = i - QPAD
#define QPAD 512
#define QSTRIDE 1760            // 512 + 736 + 512

// ---- device-global scratch ----
__device__ float4 g_trig[V];               // (cb*DSD/DU, sb*DSD/DU, cb, sb)
// quad-interleaved filtered rows: slot (vv, i) holds 4x float2 (q,dq) for
// views vv, vv+180, vv+360, vv+540  -> 32 bytes per slot.
__device__ float2 g_Qpk[QV * QSTRIDE * 4];
__device__ float  g_accS[NPIX];            // views   0..179 -> pixel P
__device__ float  g_acc90[NPIX];           // views 180..359 -> rot90(P)
__device__ float  g_acc180[NPIX];          // views 360..539 -> -P
__device__ float  g_acc270[NPIX];          // views 540..719 -> rot270(P)

// ---------------------------------------------------------------------------
// Kernel 1: cosine weight + Ram-Lak conv (parity-packed, register-tiled),
// one block (192 thr) per view. Writes trig table + quad-packed (q, dq) rows.
// ---------------------------------------------------------------------------
__global__ __launch_bounds__(192) void filter_kernel(const float* __restrict__ sino) {
    __shared__ __align__(16) float wo_s[WLEN];
    __shared__ __align__(16) float we_s[WLEN];
    __shared__ __align__(16) float ho_s[NTAPS];
    __shared__ float qrow[U];

    const int v = blockIdx.x;
    const int tid = threadIdx.x;

    for (int i = tid; i < WLEN; i += 192) { wo_s[i] = 0.0f; we_s[i] = 0.0f; }
    for (int k = tid; k < NTAPS; k += 192) {
        float d = (float)(PI_D * DU_D) * (float)(2 * k + 1);
        ho_s[k] = -1.0f / (d * d);
    }
    if (tid == 0) {
        float bf = (float)(2.0 * PI_D * (double)v / (double)V);
        float cb = (float)cos((double)bf);
        float sb = (float)sin((double)bf);
        float kk = (float)(DSD_D / DU_D);
        g_trig[v] = make_float4(cb * kk, sb * kk, cb, sb);
    }
    __syncthreads();

    {
        const float* row = sino + v * U;
        const float dsd  = (float)DSD_D;
        const float dsd2 = (float)(DSD_D * DSD_D);
        const float du   = (float)DU_D;
        for (int u = tid; u < U; u += 192) {
            float us = ((float)u - 367.5f) * du;
            float w = row[u] * (dsd * rsqrtf(dsd2 + us * us));
            if (u & 1) wo_s[PADE + (u >> 1)] = w;
            else       we_s[PODD + (u >> 1)] = w;
        }
    }
    __syncthreads();

    const int grp = tid / 96;
    const int t   = tid % 96;
    if (t < 92) {
        const int b = 4 * t;
        const float* A = grp ? (we_s + PODD + 1) : (wo_s + PADE);
        const float* C = grp ? (wo_s + PADE)     : (we_s + PODD);
        const float h0 = (float)(1.0 / (4.0 * DU_D * DU_D));

        float acc0 = h0 * C[b + 0];
        float acc1 = h0 * C[b + 1];
        float acc2 = h0 * C[b + 2];
        float acc3 = h0 * C[b + 3];

        float4 Llo = *(const float4*)(A + b - 4);
        float4 Lhi = *(const float4*)(A + b);
        float4 rlo = *(const float4*)(A + b);
        float4 rhi = *(const float4*)(A + b + 4);

        #pragma unroll 4
        for (int j = 0; j < 92; j++) {
            float4 h4 = *(const float4*)(ho_s + 4 * j);
            acc0 += h4.x * (Llo.w + rlo.x);
            acc1 += h4.x * (Lhi.x + rlo.y);
            acc2 += h4.x * (Lhi.y + rlo.z);
            acc3 += h4.x * (Lhi.z + rlo.w);
            acc0 += h4.y * (Llo.z + rlo.y);
            acc1 += h4.y * (Llo.w + rlo.z);
            acc2 += h4.y * (Lhi.x + rlo.w);
            acc3 += h4.y * (Lhi.y + rhi.x);
            acc0 += h4.z * (Llo.y + rlo.z);
            acc1 += h4.z * (Llo.z + rlo.w);
            acc2 += h4.z * (Llo.w + rhi.x);
            acc3 += h4.z * (Lhi.x + rhi.y);
            acc0 += h4.w * (Llo.x + rlo.w);
            acc1 += h4.w * (Llo.y + rhi.x);
            acc2 += h4.w * (Llo.z + rhi.y);
            acc3 += h4.w * (Llo.w + rhi.z);
            Lhi = Llo;
            Llo = *(const float4*)(A + b - 4 * j - 8);
            rlo = rhi;
            rhi = *(const float4*)(A + b + 4 * j + 8);
        }

        const float du = (float)DU_D;
        const int u0 = 8 * t + grp;
        qrow[u0 + 0] = du * acc0;
        qrow[u0 + 2] = du * acc1;
        qrow[u0 + 4] = du * acc2;
        qrow[u0 + 6] = du * acc3;
    }
    __syncthreads();

    // quad-packed (q, dq): slot i <-> u = i - QPAD; quadrant = v/180.
    // EXACT reference masking: (0,0) outside [0, U-2].
    {
        const int quad = v / QV;
        const int vv   = v - quad * QV;
        float2* dst = g_Qpk + quad;        // element stride 4 per slot
        const long long base = (long long)vv * QSTRIDE;
        for (int i = tid; i < QSTRIDE; i += 192) {
            int s = i - QPAD;
            bool in = (s >= 0) && (s <= U - 2);
            float q0 = in ? qrow[s] : 0.0f;
            float q1 = in ? qrow[s + 1] : 0.0f;
            dst[(base + i) * 4] = make_float2(q0, q1 - q0);
        }
    }
}

// ---------------------------------------------------------------------------
// Kernel 2: 4-fold symmetric backprojection over views 0..179.
// Quad-packed rows: one slot fetch (2x LDG.128) serves all 4 quadrants.
// Warp lane tile 8(iy) x 4(ix) minimizes detector-index span per warp.
// Block = 256 thr covering a 16x16 pixel tile; grid 32x32.
// ---------------------------------------------------------------------------
#define M23 8388608.0f                        // 2^23
#define ADDR_BIAS (0x4B000000ULL * 32ULL)     // magic-float bias * 32 B/slot
#define ROWB ((unsigned long long)QSTRIDE * 32ULL)

__global__ __launch_bounds__(256, 4) void bp_kernel() {
    __shared__ __align__(16) float4 strig[QV];

    const int tid = threadIdx.x;
    for (int i = tid; i < QV; i += 256) strig[i] = g_trig[i];
    __syncthreads();

    const int lane = tid & 31;
    const int w    = tid >> 5;               // 0..7
    const int iy = blockIdx.x * 16 + (w & 1) * 8 + (lane & 7);
    const int ix = blockIdx.y * 16 + (w >> 1) * 4 + (lane >> 3);

    const float dx  = (float)(SVOX_D / (double)NXY);
    const float y   = ((float)iy - 255.5f) * dx;
    const float x   = ((float)ix - 255.5f) * dx;
    const float c0  = 367.5f + (float)QPAD;
    const float dso = (float)DSO_D;

    unsigned long long pa = (unsigned long long)(const char*)g_Qpk - ADDR_BIAS;

    float accS = 0.0f, acc90 = 0.0f, acc180 = 0.0f, acc270 = 0.0f;

    #pragma unroll 4
    for (int v = 0; v < QV; v++, pa += ROWB) {
        float4 tg = strig[v];

        float t = fmaf(x, tg.x, y * tg.y);
        float D = fmaf(x, tg.w, fmaf(-y, tg.z, dso));
        float r;
        asm("rcp.approx.f32 %0, %1;" : "=f"(r) : "f"(D));
        float idx = fmaf(t, r, c0);
        float m = __fadd_rd(idx, M23);

        unsigned long long a = pa + (unsigned long long)__float_as_uint(m) * 32ULL;
        float4 qA = __ldg((const float4*)a);          // (q0,dq0,q1,dq1)
        float4 qB = __ldg((const float4*)(a + 16));   // (q2,dq2,q3,dq3)

        float f = idx - (m - M23);
        float w2 = r * r;

        accS   = fmaf(fmaf(f, qA.y, qA.x), w2, accS);
        acc90  = fmaf(fmaf(f, qA.w, qA.z), w2, acc90);
        acc180 = fmaf(fmaf(f, qB.y, qB.x), w2, acc180);
        acc270 = fmaf(fmaf(f, qB.w, qB.z), w2, acc270);
    }

    const int p = ix * NXY + iy;
    g_accS[p]   = accS;
    g_acc90[p]  = acc90;
    g_acc180[p] = acc180;
    g_acc270[p] = acc270;
}

// ---------------------------------------------------------------------------
// Kernel 3: combine. For output O=(ix,iy):
//   out[O] = scale * ( S[O] + acc90[rot270(O)] + acc180[-O] + acc270[rot90(O)] )
// rot90(ix,iy)=(511-iy,ix); rot270(ix,iy)=(iy,511-ix); -O = (511-ix,511-iy).
// ---------------------------------------------------------------------------
__global__ __launch_bounds__(256) void combine_kernel(float* __restrict__ out) {
    const int i = blockIdx.x * 256 + threadIdx.x;
    const int ix = i >> 9;
    const int iy = i & 511;
    const float scale = (float)(0.5 * (2.0 * PI_D / (double)V) * DSO_D * DSO_D);

    float s   = g_accS[i];
    float a18 = g_acc180[NPIX - 1 - i];
    float a9  = g_acc90[iy * NXY + (NXY - 1 - ix)];    // P = rot270(O)
    float a27 = g_acc270[(NXY - 1 - iy) * NXY + ix];   // P = rot90(O)

    out[i] = (s + a9 + a18 + a27) * scale;
}

// ---------------------------------------------------------------------------
extern "C" void kernel_launch(void* const* d_in, const int* in_sizes, int n_in,
                              void* d_out, int out_size) {
    (void)in_sizes; (void)n_in; (void)out_size;
    const float* sino = (const float*)d_in[0];
    float* out = (float*)d_out;

    filter_kernel<<<V, 192>>>(sino);
    dim3 bpBlock(256);
    dim3 bpGrid(NXY / 16, NXY / 16);    // 32 x 32 = 1024 blocks
    bp_kernel<<<bpGrid, bpBlock>>>();
    combine_kernel<<<NPIX / 256, 256>>>(out);
}

// round 13
// speedup vs baseline: 1.3949x; 1.3949x over previous
#include <cuda_runtime.h>
#include <math.h>

#define V 720
#define QV 180
#define U 736
#define NXY 512
#define NPIX (NXY * NXY)
#define NTAPS 368

#define DU_D   1.2858
#define DSO_D  595.0
#define DOD_D  490.6
#define DSD_D  (DSO_D + DOD_D)
#define SVOX_D 400.0
#define PI_D   3.14159265358979323846

// parity-packed conv arrays
#define PADE 380
#define PODD 383
#define WLEN 1124

// guard-band padded filtered rows: slot i holds detector index u = i - QPAD
#define QPAD 512
#define QSTRIDE 1760            // 512 + 736 + 512

// ---- device-global scratch ----
__device__ float4 g_trig[V];          // (cb*DSD/DU, sb*DSD/DU, cb, sb)
__device__ float2 g_Qp[V * QSTRIDE];  // (Q[u], Q[u+1]-Q[u]); (0,0) outside [0,U-2]
__device__ float  g_accS[NPIX];       // views   0..179 -> pixel P
__device__ float  g_acc90[NPIX];      // views 180..359 -> rot90(P)
__device__ float  g_acc180[NPIX];     // views 360..539 -> -P
__device__ float  g_acc270[NPIX];     // views 540..719 -> rot270(P)

// ---------------------------------------------------------------------------
// Kernel 1: cosine weight + Ram-Lak conv (parity-packed, register-tiled),
// one block (192 thr) per view. Writes trig table + padded (q, dq) rows.
// ---------------------------------------------------------------------------
__global__ __launch_bounds__(192) void filter_kernel(const float* __restrict__ sino) {
    __shared__ __align__(16) float wo_s[WLEN];
    __shared__ __align__(16) float we_s[WLEN];
    __shared__ __align__(16) float ho_s[NTAPS];
    __shared__ float qrow[U];

    const int v = blockIdx.x;
    const int tid = threadIdx.x;

    for (int i = tid; i < WLEN; i += 192) { wo_s[i] = 0.0f; we_s[i] = 0.0f; }
    for (int k = tid; k < NTAPS; k += 192) {
        float d = (float)(PI_D * DU_D) * (float)(2 * k + 1);
        ho_s[k] = -1.0f / (d * d);
    }
    if (tid == 0) {
        float bf = (float)(2.0 * PI_D * (double)v / (double)V);
        float cb = (float)cos((double)bf);
        float sb = (float)sin((double)bf);
        float kk = (float)(DSD_D / DU_D);
        g_trig[v] = make_float4(cb * kk, sb * kk, cb, sb);
    }
    __syncthreads();

    {
        const float* row = sino + v * U;
        const float dsd  = (float)DSD_D;
        const float dsd2 = (float)(DSD_D * DSD_D);
        const float du   = (float)DU_D;
        for (int u = tid; u < U; u += 192) {
            float us = ((float)u - 367.5f) * du;
            float w = row[u] * (dsd * rsqrtf(dsd2 + us * us));
            if (u & 1) wo_s[PADE + (u >> 1)] = w;
            else       we_s[PODD + (u >> 1)] = w;
        }
    }
    __syncthreads();

    const int grp = tid / 96;
    const int t   = tid % 96;
    if (t < 92) {
        const int b = 4 * t;
        const float* A = grp ? (we_s + PODD + 1) : (wo_s + PADE);
        const float* C = grp ? (wo_s + PADE)     : (we_s + PODD);
        const float h0 = (float)(1.0 / (4.0 * DU_D * DU_D));

        float acc0 = h0 * C[b + 0];
        float acc1 = h0 * C[b + 1];
        float acc2 = h0 * C[b + 2];
        float acc3 = h0 * C[b + 3];

        float4 Llo = *(const float4*)(A + b - 4);
        float4 Lhi = *(const float4*)(A + b);
        float4 rlo = *(const float4*)(A + b);
        float4 rhi = *(const float4*)(A + b + 4);

        #pragma unroll 4
        for (int j = 0; j < 92; j++) {
            float4 h4 = *(const float4*)(ho_s + 4 * j);
            acc0 += h4.x * (Llo.w + rlo.x);
            acc1 += h4.x * (Lhi.x + rlo.y);
            acc2 += h4.x * (Lhi.y + rlo.z);
            acc3 += h4.x * (Lhi.z + rlo.w);
            acc0 += h4.y * (Llo.z + rlo.y);
            acc1 += h4.y * (Llo.w + rlo.z);
            acc2 += h4.y * (Lhi.x + rlo.w);
            acc3 += h4.y * (Lhi.y + rhi.x);
            acc0 += h4.z * (Llo.y + rlo.z);
            acc1 += h4.z * (Llo.z + rlo.w);
            acc2 += h4.z * (Llo.w + rhi.x);
            acc3 += h4.z * (Lhi.x + rhi.y);
            acc0 += h4.w * (Llo.x + rlo.w);
            acc1 += h4.w * (Llo.y + rhi.x);
            acc2 += h4.w * (Llo.z + rhi.y);
            acc3 += h4.w * (Llo.w + rhi.z);
            Lhi = Llo;
            Llo = *(const float4*)(A + b - 4 * j - 8);
            rlo = rhi;
            rhi = *(const float4*)(A + b + 4 * j + 8);
        }

        const float du = (float)DU_D;
        const int u0 = 8 * t + grp;
        qrow[u0 + 0] = du * acc0;
        qrow[u0 + 2] = du * acc1;
        qrow[u0 + 4] = du * acc2;
        qrow[u0 + 6] = du * acc3;
    }
    __syncthreads();

    // padded (q, dq) pairs: slot i <-> u = i - QPAD.
    // EXACT reference masking: (0,0) outside [0, U-2].
    {
        float2* dst = g_Qp + v * QSTRIDE;
        for (int i = tid; i < QSTRIDE; i += 192) {
            int s = i - QPAD;
            bool in = (s >= 0) && (s <= U - 2);
            float q0 = in ? qrow[s] : 0.0f;
            float q1 = in ? qrow[s + 1] : 0.0f;
            dst[i] = make_float2(q0, q1 - q0);
        }
    }
}

// ---------------------------------------------------------------------------
// Kernel 2: 4-fold symmetric backprojection over views 0..179.
// Geometry (u, w) for (P, v) is bit-identical for (rot90 P, v+180),
// (-P, v+360), (rot270 P, v+540). One eval -> 4 accumulations from
// rows v, v+180, v+360, v+540 (separate LDG.64, constant byte offsets).
// Lane map: warp = 16(iy) x 2(ix) tile -> ~2x smaller detector-index span
// per warp than 32x1, cutting L1 wavefronts per load.
// Block = 256 thr covering 16x16 pixels; grid 32x32.
// ---------------------------------------------------------------------------
#define M23 8388608.0f                       // 2^23
#define ADDR_BIAS 0x258000000ULL             // 0x4B000000 * sizeof(float2)
#define ROWB ((unsigned long long)QSTRIDE * 8ULL)
#define R180B (180ULL * ROWB)                // 2,534,400 bytes

__global__ __launch_bounds__(256, 4) void bp_kernel() {
    __shared__ __align__(16) float4 strig[QV];

    const int tid = threadIdx.x;
    for (int i = tid; i < QV; i += 256) strig[i] = g_trig[i];
    __syncthreads();

    const int lane = tid & 31;
    const int wp   = tid >> 5;               // 0..7
    const int iy = blockIdx.x * 16 + (lane & 15);
    const int ix = blockIdx.y * 16 + wp * 2 + (lane >> 4);

    const float dx  = (float)(SVOX_D / (double)NXY);
    const float y   = ((float)iy - 255.5f) * dx;
    const float x   = ((float)ix - 255.5f) * dx;
    const float c0  = 367.5f + (float)QPAD;
    const float dso = (float)DSO_D;

    unsigned long long pa = (unsigned long long)(const char*)g_Qp - ADDR_BIAS;

    float accS = 0.0f, acc90 = 0.0f, acc180 = 0.0f, acc270 = 0.0f;

    #pragma unroll 4
    for (int v = 0; v < QV; v++, pa += ROWB) {
        float4 tg = strig[v];

        float t = fmaf(x, tg.x, y * tg.y);
        float D = fmaf(x, tg.w, fmaf(-y, tg.z, dso));
        float r;
        asm("rcp.approx.f32 %0, %1;" : "=f"(r) : "f"(D));
        float idx = fmaf(t, r, c0);
        float m = __fadd_rd(idx, M23);

        unsigned long long a = pa + (unsigned long long)__float_as_uint(m) * 8ULL;
        float2 q0 = __ldg((const float2*)a);
        float2 q1 = __ldg((const float2*)(a + R180B));
        float2 q2 = __ldg((const float2*)(a + 2ULL * R180B));
        float2 q3 = __ldg((const float2*)(a + 3ULL * R180B));

        float f = idx - (m - M23);
        float w = r * r;

        accS   = fmaf(fmaf(f, q0.y, q0.x), w, accS);
        acc90  = fmaf(fmaf(f, q1.y, q1.x), w, acc90);
        acc180 = fmaf(fmaf(f, q2.y, q2.x), w, acc180);
        acc270 = fmaf(fmaf(f, q3.y, q3.x), w, acc270);
    }

    const int p = ix * NXY + iy;
    g_accS[p]   = accS;
    g_acc90[p]  = acc90;
    g_acc180[p] = acc180;
    g_acc270[p] = acc270;
}

// ---------------------------------------------------------------------------
// Kernel 3: combine. For output O=(ix,iy):
//   out[O] = scale * ( S[O] + acc90[rot270(O)] + acc180[-O] + acc270[rot90(O)] )
// rot90(ix,iy)=(511-iy,ix); rot270(ix,iy)=(iy,511-ix); -O = (511-ix,511-iy).
// ---------------------------------------------------------------------------
__global__ __launch_bounds__(256) void combine_kernel(float* __restrict__ out) {
    const int i = blockIdx.x * 256 + threadIdx.x;
    const int ix = i >> 9;
    const int iy = i & 511;
    const float scale = (float)(0.5 * (2.0 * PI_D / (double)V) * DSO_D * DSO_D);

    float s   = g_accS[i];
    float a18 = g_acc180[NPIX - 1 - i];
    float a9  = g_acc90[iy * NXY + (NXY - 1 - ix)];    // P = rot270(O)
    float a27 = g_acc270[(NXY - 1 - iy) * NXY + ix];   // P = rot90(O)

    out[i] = (s + a9 + a18 + a27) * scale;
}

// ---------------------------------------------------------------------------
extern "C" void kernel_launch(void* const* d_in, const int* in_sizes, int n_in,
                              void* d_out, int out_size) {
    (void)in_sizes; (void)n_in; (void)out_size;
    const float* sino = (const float*)d_in[0];
    float* out = (float*)d_out;

    filter_kernel<<<V, 192>>>(sino);
    dim3 bpBlock(256);
    dim3 bpGrid(NXY / 16, NXY / 16);    // 32 x 32 = 1024 blocks
    bp_kernel<<<bpGrid, bpBlock>>>();
    combine_kernel<<<NPIX / 256, 256>>>(out);
}

// round 14
// speedup vs baseline: 1.4070x; 1.0086x over previous
#include <cuda_runtime.h>
#include <math.h>

#define V 720
#define QV 180
#define U 736
#define NXY 512
#define NPIX (NXY * NXY)
#define NTAPS 368

#define DU_D   1.2858
#define DSO_D  595.0
#define DOD_D  490.6
#define DSD_D  (DSO_D + DOD_D)
#define SVOX_D 400.0
#define PI_D   3.14159265358979323846

// parity-packed conv arrays
#define PADE 380
#define PODD 383
#define WLEN 1124

// guard-band padded filtered rows: slot i holds detector index u = i - QPAD
#define QPAD 512
#define QSTRIDE 1760            // 512 + 736 + 512

// ---- device-global scratch ----
__device__ float4 g_trig[V];          // (cb*DSD/DU, sb*DSD/DU, cb, sb)
__device__ float2 g_Qp[V * QSTRIDE];  // (Q[u], Q[u+1]-Q[u]); (0,0) outside [0,U-2]
__device__ float  g_accS[NPIX];       // views   0..179 -> pixel P
__device__ float  g_acc90[NPIX];      // views 180..359 -> rot90(P)
__device__ float  g_acc180[NPIX];     // views 360..539 -> -P
__device__ float  g_acc270[NPIX];     // views 540..719 -> rot270(P)

// ---------------------------------------------------------------------------
// Kernel 1: cosine weight + Ram-Lak conv, parity-packed + register-tiled,
// with split left/right tap loops bounded per warp (skip guaranteed-zero
// taps; each warp's outputs span a 256-wide u-chunk so bounds are uniform).
// Results bit-identical to the full-range version (skipped terms are h*0).
// ---------------------------------------------------------------------------
__global__ __launch_bounds__(192) void filter_kernel(const float* __restrict__ sino) {
    __shared__ __align__(16) float wo_s[WLEN];
    __shared__ __align__(16) float we_s[WLEN];
    __shared__ __align__(16) float ho_s[NTAPS];
    __shared__ float qrow[U];

    const int v = blockIdx.x;
    const int tid = threadIdx.x;

    for (int i = tid; i < WLEN; i += 192) { wo_s[i] = 0.0f; we_s[i] = 0.0f; }
    for (int k = tid; k < NTAPS; k += 192) {
        float d = (float)(PI_D * DU_D) * (float)(2 * k + 1);
        ho_s[k] = -1.0f / (d * d);
    }
    if (tid == 0) {
        float bf = (float)(2.0 * PI_D * (double)v / (double)V);
        float cb = (float)cos((double)bf);
        float sb = (float)sin((double)bf);
        float kk = (float)(DSD_D / DU_D);
        g_trig[v] = make_float4(cb * kk, sb * kk, cb, sb);
    }
    __syncthreads();

    {
        const float* row = sino + v * U;
        const float dsd  = (float)DSD_D;
        const float dsd2 = (float)(DSD_D * DSD_D);
        const float du   = (float)DU_D;
        for (int u = tid; u < U; u += 192) {
            float us = ((float)u - 367.5f) * du;
            float w = row[u] * (dsd * rsqrtf(dsd2 + us * us));
            if (u & 1) wo_s[PADE + (u >> 1)] = w;
            else       we_s[PODD + (u >> 1)] = w;
        }
    }
    __syncthreads();

    const int grp = tid / 96;
    const int t   = tid % 96;
    const int wi  = t >> 5;                 // warp-chunk index 0..2 (uniform/warp)
    if (t < 92) {
        const int b = 4 * t;
        const float* A = grp ? (we_s + PODD + 1) : (wo_s + PADE);
        const float* C = grp ? (wo_s + PADE)     : (we_s + PODD);
        const float h0 = (float)(1.0 / (4.0 * DU_D * DU_D));

        float acc0 = h0 * C[b + 0];
        float acc1 = h0 * C[b + 1];
        float acc2 = h0 * C[b + 2];
        float acc3 = h0 * C[b + 3];

        const int JL = min(32 * wi + 32, 92);   // left taps needed by this warp
        const int JR = 92 - 32 * wi;            // right taps needed by this warp

        // ---- left-side taps ----
        {
            float4 Llo = *(const float4*)(A + b - 4);
            float4 Lhi = *(const float4*)(A + b);
            #pragma unroll 4
            for (int j = 0; j < JL; j++) {
                float4 h4 = *(const float4*)(ho_s + 4 * j);
                acc0 += h4.x * Llo.w;
                acc1 += h4.x * Lhi.x;
                acc2 += h4.x * Lhi.y;
                acc3 += h4.x * Lhi.z;
                acc0 += h4.y * Llo.z;
                acc1 += h4.y * Llo.w;
                acc2 += h4.y * Lhi.x;
                acc3 += h4.y * Lhi.y;
                acc0 += h4.z * Llo.y;
                acc1 += h4.z * Llo.z;
                acc2 += h4.z * Llo.w;
                acc3 += h4.z * Lhi.x;
                acc0 += h4.w * Llo.x;
                acc1 += h4.w * Llo.y;
                acc2 += h4.w * Llo.z;
                acc3 += h4.w * Llo.w;
                Lhi = Llo;
                Llo = *(const float4*)(A + b - 4 * j - 8);
            }
        }

        // ---- right-side taps ----
        {
            float4 rlo = *(const float4*)(A + b);
            float4 rhi = *(const float4*)(A + b + 4);
            #pragma unroll 4
            for (int j = 0; j < JR; j++) {
                float4 h4 = *(const float4*)(ho_s + 4 * j);
                acc0 += h4.x * rlo.x;
                acc1 += h4.x * rlo.y;
                acc2 += h4.x * rlo.z;
                acc3 += h4.x * rlo.w;
                acc0 += h4.y * rlo.y;
                acc1 += h4.y * rlo.z;
                acc2 += h4.y * rlo.w;
                acc3 += h4.y * rhi.x;
                acc0 += h4.z * rlo.z;
                acc1 += h4.z * rlo.w;
                acc2 += h4.z * rhi.x;
                acc3 += h4.z * rhi.y;
                acc0 += h4.w * rlo.w;
                acc1 += h4.w * rhi.x;
                acc2 += h4.w * rhi.y;
                acc3 += h4.w * rhi.z;
                rlo = rhi;
                rhi = *(const float4*)(A + b + 4 * j + 8);
            }
        }

        const float du = (float)DU_D;
        const int u0 = 8 * t + grp;
        qrow[u0 + 0] = du * acc0;
        qrow[u0 + 2] = du * acc1;
        qrow[u0 + 4] = du * acc2;
        qrow[u0 + 6] = du * acc3;
    }
    __syncthreads();

    // padded (q, dq) pairs: slot i <-> u = i - QPAD.
    // EXACT reference masking: (0,0) outside [0, U-2].
    {
        float2* dst = g_Qp + v * QSTRIDE;
        for (int i = tid; i < QSTRIDE; i += 192) {
            int s = i - QPAD;
            bool in = (s >= 0) && (s <= U - 2);
            float q0 = in ? qrow[s] : 0.0f;
            float q1 = in ? qrow[s + 1] : 0.0f;
            dst[i] = make_float2(q0, q1 - q0);
        }
    }
}

// ---------------------------------------------------------------------------
// Kernel 2: 4-fold symmetric backprojection over views 0..179 (R11 config).
// One geometry eval -> 4 accumulations from rows v, v+180, v+360, v+540.
// Block (32,8): iy = bx*32+tx, ix = by*8+ty; grid 16x64.
// ---------------------------------------------------------------------------
#define M23 8388608.0f                       // 2^23
#define ADDR_BIAS 0x258000000ULL             // 0x4B000000 * sizeof(float2)
#define ROWB ((unsigned long long)QSTRIDE * 8ULL)
#define R180B (180ULL * ROWB)                // 2,534,400 bytes

__global__ __launch_bounds__(256, 4) void bp_kernel() {
    __shared__ __align__(16) float4 strig[QV];

    const int tid = threadIdx.y * 32 + threadIdx.x;
    for (int i = tid; i < QV; i += 256) strig[i] = g_trig[i];
    __syncthreads();

    const int iy = blockIdx.x * 32 + threadIdx.x;
    const int ix = blockIdx.y * 8 + threadIdx.y;

    const float dx  = (float)(SVOX_D / (double)NXY);
    const float y   = ((float)iy - 255.5f) * dx;
    const float x   = ((float)ix - 255.5f) * dx;
    const float c0  = 367.5f + (float)QPAD;
    const float dso = (float)DSO_D;

    unsigned long long pa = (unsigned long long)(const char*)g_Qp - ADDR_BIAS;

    float accS = 0.0f, acc90 = 0.0f, acc180 = 0.0f, acc270 = 0.0f;

    #pragma unroll 4
    for (int v = 0; v < QV; v++, pa += ROWB) {
        float4 tg = strig[v];

        float t = fmaf(x, tg.x, y * tg.y);
        float D = fmaf(x, tg.w, fmaf(-y, tg.z, dso));
        float r;
        asm("rcp.approx.f32 %0, %1;" : "=f"(r) : "f"(D));
        float idx = fmaf(t, r, c0);
        float m = __fadd_rd(idx, M23);

        unsigned long long a = pa + (unsigned long long)__float_as_uint(m) * 8ULL;
        float2 q0 = __ldg((const float2*)a);
        float2 q1 = __ldg((const float2*)(a + R180B));
        float2 q2 = __ldg((const float2*)(a + 2ULL * R180B));
        float2 q3 = __ldg((const float2*)(a + 3ULL * R180B));

        float f = idx - (m - M23);
        float w = r * r;

        accS   = fmaf(fmaf(f, q0.y, q0.x), w, accS);
        acc90  = fmaf(fmaf(f, q1.y, q1.x), w, acc90);
        acc180 = fmaf(fmaf(f, q2.y, q2.x), w, acc180);
        acc270 = fmaf(fmaf(f, q3.y, q3.x), w, acc270);
    }

    const int p = ix * NXY + iy;
    g_accS[p]   = accS;
    g_acc90[p]  = acc90;
    g_acc180[p] = acc180;
    g_acc270[p] = acc270;
}

// ---------------------------------------------------------------------------
// Kernel 3: combine. For output O=(ix,iy):
//   out[O] = scale * ( S[O] + acc90[rot270(O)] + acc180[-O] + acc270[rot90(O)] )
// rot90(ix,iy)=(511-iy,ix); rot270(ix,iy)=(iy,511-ix); -O = (511-ix,511-iy).
// ---------------------------------------------------------------------------
__global__ __launch_bounds__(256) void combine_kernel(float* __restrict__ out) {
    const int i = blockIdx.x * 256 + threadIdx.x;
    const int ix = i >> 9;
    const int iy = i & 511;
    const float scale = (float)(0.5 * (2.0 * PI_D / (double)V) * DSO_D * DSO_D);

    float s   = g_accS[i];
    float a18 = g_acc180[NPIX - 1 - i];
    float a9  = g_acc90[iy * NXY + (NXY - 1 - ix)];    // P = rot270(O)
    float a27 = g_acc270[(NXY - 1 - iy) * NXY + ix];   // P = rot90(O)

    out[i] = (s + a9 + a18 + a27) * scale;
}

// ---------------------------------------------------------------------------
extern "C" void kernel_launch(void* const* d_in, const int* in_sizes, int n_in,
                              void* d_out, int out_size) {
    (void)in_sizes; (void)n_in; (void)out_size;
    const float* sino = (const float*)d_in[0];
    float* out = (float*)d_out;

    filter_kernel<<<V, 192>>>(sino);
    dim3 bpBlock(32, 8);
    dim3 bpGrid(NXY / 32, NXY / 8);     // 16 x 64 = 1024 blocks
    bp_kernel<<<bpGrid, bpBlock>>>();
    combine_kernel<<<NPIX / 256, 256>>>(out);
}